// round 8
// baseline (speedup 1.0000x reference)
#include <cuda_runtime.h>
#include <cstdint>

#define HID   256
#define BB    8
#define TT    16
#define INSZ  784
#define OUTSZ 128

// scratch (no device allocs allowed)
__device__ float g_seq[TT * BB * INSZ];       // [t][b][784]

// ---------------- f32x2 helpers ----------------
__device__ __forceinline__ unsigned long long pk2(float a, float b) {
    unsigned long long r;
    asm("mov.b64 %0, {%1,%2};" : "=l"(r) : "f"(a), "f"(b));
    return r;
}
__device__ __forceinline__ float2 upk2(unsigned long long v) {
    float2 f;
    asm("mov.b64 {%0,%1}, %2;" : "=f"(f.x), "=f"(f.y) : "l"(v));
    return f;
}
__device__ __forceinline__ void ffma2(unsigned long long& d,
                                      unsigned long long a,
                                      unsigned long long b) {
    asm("fma.rn.f32x2 %0, %1, %2, %0;" : "+l"(d) : "l"(a), "l"(b));
}
__device__ __forceinline__ uint32_t smem_u32(const void* p) {
    uint32_t a;
    asm("{ .reg .u64 t; cvta.to.shared.u64 t, %1; cvt.u32.u64 %0, t; }"
        : "=r"(a) : "l"(p));
    return a;
}
__device__ __forceinline__ void cluster_sync_() {
    asm volatile("barrier.cluster.arrive.aligned;" ::: "memory");
    asm volatile("barrier.cluster.wait.aligned;"   ::: "memory");
}
// async remote store with tx-completion on the target CTA's mbarrier
__device__ __forceinline__ void st_async_f32(uint32_t dst_local, uint32_t bar_local,
                                             int rank, float v) {
    asm volatile(
        "{ .reg .b32 rd, rb;\n\t"
        "mapa.shared::cluster.u32 rd, %0, %2;\n\t"
        "mapa.shared::cluster.u32 rb, %1, %2;\n\t"
        "st.async.shared::cluster.mbarrier::complete_tx::bytes.f32 [rd], %3, [rb];\n\t"
        "}"
        :: "r"(dst_local), "r"(bar_local), "r"(rank), "f"(v) : "memory");
}
__device__ __forceinline__ void mbar_init(uint32_t bar, unsigned cnt) {
    asm volatile("mbarrier.init.shared.b64 [%0], %1;" :: "r"(bar), "r"(cnt) : "memory");
}
__device__ __forceinline__ void mbar_expect_tx(uint32_t bar, unsigned bytes) {
    asm volatile("mbarrier.arrive.expect_tx.shared.b64 _, [%0], %1;"
                 :: "r"(bar), "r"(bytes) : "memory");
}
__device__ __forceinline__ void mbar_wait_parity(uint32_t bar, unsigned parity) {
    asm volatile(
        "{ .reg .pred P;\n\t"
        "WL%=:\n\t"
        "mbarrier.try_wait.parity.acquire.cluster.shared::cta.b64 P, [%0], %1, 0x989680;\n\t"
        "@P bra WD%=;\n\t"
        "bra WL%=;\n\t"
        "WD%=:\n\t"
        "}"
        :: "r"(bar), "r"(parity) : "memory");
}
__device__ __forceinline__ float sigm(float x) {
    return 1.0f / (1.0f + __expf(-x));
}
__device__ __forceinline__ float tanh_fast(float x) {
    return 2.0f / (1.0f + __expf(-2.0f * x)) - 1.0f;
}

// =====================================================================
// Kernel 1: fused 3D+2D adaptive avg pool (R6/R7-proven, at DRAM roofline).
// =====================================================================
__global__ void pool_kernel(const float* __restrict__ x) {
    int gwarp = (blockIdx.x * blockDim.x + threadIdx.x) >> 5;
    int lane  = threadIdx.x & 31;

    int h2 = gwarp % 7;  int tmp = gwarp / 7;
    int d2 = tmp % 16;   tmp /= 16;
    int c  = tmp % 16;   tmp /= 16;
    int b  = tmp;        // 0..7

    const float* base = x + (((long long)(b * 16 + c) * 32 + d2 * 2) * 112
                             + h2 * 16) * 112;
    float acc0 = 0.0f, acc1 = 0.0f;
    if (lane < 28) {
        #pragma unroll
        for (int dd = 0; dd < 2; dd++) {
            #pragma unroll 8
            for (int hh = 0; hh < 16; hh += 2) {
                const float4* r0 = (const float4*)(base + dd * 12544 + hh * 112);
                const float4* r1 = (const float4*)(base + dd * 12544 + (hh + 1) * 112);
                float4 v0 = __ldcs(r0 + lane);
                float4 v1 = __ldcs(r1 + lane);
                acc0 += (v0.x + v0.y) + (v0.z + v0.w);
                acc1 += (v1.x + v1.y) + (v1.z + v1.w);
            }
        }
    }
    float acc = acc0 + acc1;
    acc += __shfl_down_sync(0xffffffffu, acc, 2);
    acc += __shfl_down_sync(0xffffffffu, acc, 1);
    if (lane < 28 && (lane & 3) == 0) {
        int w2 = lane >> 2;
        g_seq[(d2 * BB + b) * INSZ + c * 49 + h2 * 7 + w2] = acc * (1.0f / 512.0f);
    }
}

// =====================================================================
// Kernel 2: FUSED gi-GEMM + GRU + head. One 8-CTA cluster per batch.
// Phase A (gi): thread (jl = tid>>3, s = tid&7) accumulates
//   acc[g][t] = sum_{k in slice(s)} Wih[g*256+rank*32+jl][k] * seq[t][b][k]
// over k-slice [s*96, s*96+96) + tail pair (768+2s, +1). No smem staging:
// W via aligned LDG.128 (4 rows x 8 k-offsets per warp), seq via LDG.128
// (4-way same-address merge; 50 KB slice L1-resident). Width-8 butterfly
// reduce -> every lane holds full sums; lane s writes t = 2s, 2s+1 (+bias)
// into gis smem. Then W_hh -> registers, and the R7-proven mbarrier
// ping-pong GRU step loop + output head.
// =====================================================================
__global__ void __launch_bounds__(256, 1) __cluster_dims__(8, 1, 1)
gru_kernel(const float* __restrict__ Wih,
           const float* __restrict__ bih,
           const float* __restrict__ Whh,
           const float* __restrict__ bhh,
           const float* __restrict__ Wout,
           const float* __restrict__ bout,
           float* __restrict__ out) {
    __shared__ float hs[3][264];     // triple-buffered h (swizzled), 256+pad
    __shared__ float gis[TT][96];    // gi[t][g*32+jl] for this (b, rank)
    __shared__ __align__(8) unsigned long long mbar[2];

    int tid  = threadIdx.x;
    int b    = blockIdx.x >> 3;      // batch = cluster id
    int rank = blockIdx.x & 7;       // cluster rank
    int jl   = tid >> 3;             // 0..31
    int s    = tid & 7;              // 0..7
    int j    = rank * 32 + jl;       // owned hidden unit

    uint32_t bar0 = smem_u32(&mbar[0]);
    uint32_t bar1 = smem_u32(&mbar[1]);
    // zero all 3 h buffers; init barriers; post expect for step 0
    for (int q = tid; q < 3 * 264; q += 256) (&hs[0][0])[q] = 0.0f;
    if (tid == 0) {
        mbar_init(bar0, 1);
        mbar_init(bar1, 1);
        mbar_expect_tx(bar0, 1024);
    }

    // ---------------- Phase A: gi slice ----------------
    unsigned long long acc[3][TT];
    #pragma unroll
    for (int g = 0; g < 3; g++)
        #pragma unroll
        for (int t = 0; t < TT; t++) acc[g][t] = 0ull;

    {
        const float* wr0 = Wih + (long long)(0 * HID + j) * INSZ + s * 96;
        const float* wr1 = Wih + (long long)(1 * HID + j) * INSZ + s * 96;
        const float* wr2 = Wih + (long long)(2 * HID + j) * INSZ + s * 96;

        #pragma unroll 2
        for (int q = 0; q < 24; q++) {
            float4 w0 = ((const float4*)wr0)[q];
            float4 w1 = ((const float4*)wr1)[q];
            float4 w2 = ((const float4*)wr2)[q];
            unsigned long long w0a = pk2(w0.x, w0.y), w0b = pk2(w0.z, w0.w);
            unsigned long long w1a = pk2(w1.x, w1.y), w1b = pk2(w1.z, w1.w);
            unsigned long long w2a = pk2(w2.x, w2.y), w2b = pk2(w2.z, w2.w);
            #pragma unroll
            for (int t = 0; t < TT; t++) {
                float4 sv = *((const float4*)(g_seq + (t * BB + b) * INSZ + s * 96) + q);
                unsigned long long sa = pk2(sv.x, sv.y), sb = pk2(sv.z, sv.w);
                ffma2(acc[0][t], w0a, sa);  ffma2(acc[0][t], w0b, sb);
                ffma2(acc[1][t], w1a, sa);  ffma2(acc[1][t], w1b, sb);
                ffma2(acc[2][t], w2a, sa);  ffma2(acc[2][t], w2b, sb);
            }
        }
        // tail: k = 768 + 2s, 768 + 2s + 1
        {
            int kt = 768 + 2 * s;
            float2 w0t = *(const float2*)(Wih + (long long)(0 * HID + j) * INSZ + kt);
            float2 w1t = *(const float2*)(Wih + (long long)(1 * HID + j) * INSZ + kt);
            float2 w2t = *(const float2*)(Wih + (long long)(2 * HID + j) * INSZ + kt);
            unsigned long long w0p = pk2(w0t.x, w0t.y);
            unsigned long long w1p = pk2(w1t.x, w1t.y);
            unsigned long long w2p = pk2(w2t.x, w2t.y);
            #pragma unroll
            for (int t = 0; t < TT; t++) {
                float2 sv = *(const float2*)(g_seq + (t * BB + b) * INSZ + kt);
                unsigned long long sp = pk2(sv.x, sv.y);
                ffma2(acc[0][t], w0p, sp);
                ffma2(acc[1][t], w1p, sp);
                ffma2(acc[2][t], w2p, sp);
            }
        }
    }
    // width-8 butterfly reduce over s; all lanes end with full sums
    #pragma unroll
    for (int g = 0; g < 3; g++) {
        float bias = bih[g * HID + j];
        #pragma unroll
        for (int t = 0; t < TT; t++) {
            float2 f = upk2(acc[g][t]);
            float v = f.x + f.y;
            v += __shfl_xor_sync(0xffffffffu, v, 4, 8);
            v += __shfl_xor_sync(0xffffffffu, v, 2, 8);
            v += __shfl_xor_sync(0xffffffffu, v, 1, 8);
            // lane s owns t = 2s, 2s+1
            if (t == 2 * s || t == 2 * s + 1)
                gis[t][g * 32 + jl] = v + bias;
        }
    }

    // ---------------- W_hh slice into registers ----------------
    unsigned long long wp[3][16];
    #pragma unroll
    for (int g = 0; g < 3; g++) {
        const ulonglong2* ws =
            (const ulonglong2*)(Whh + (long long)(g * HID + j) * HID + s * 32);
        #pragma unroll
        for (int m = 0; m < 8; m++) {
            ulonglong2 v = ws[m];
            wp[g][2 * m]     = v.x;
            wp[g][2 * m + 1] = v.y;
        }
    }
    float bh0 = bhh[j], bh1 = bhh[HID + j], bh2 = bhh[2 * HID + j];

    __syncthreads();
    cluster_sync_();                      // gis ready, barriers inited everywhere

    // swizzled float index for my j (store target in peer buffers)
    int p_    = j >> 1;
    int slot_ = ((p_ & 15) << 3) | (p_ >> 4);
    int fidx  = 2 * slot_ + (j & 1);

    float hpv = 0.0f;                     // hprev for (b, j): all s identical

    for (int t = 0; t < TT; t++) {
        uint32_t barT = (t & 1) ? bar1 : bar0;
        if (tid == 0 && t < TT - 1)
            mbar_expect_tx((t & 1) ? bar0 : bar1, 1024);   // for step t+1

        const unsigned long long* hb = (const unsigned long long*)hs[t % 3];

        unsigned long long a0 = 0, a1 = 0, a2 = 0;
        #pragma unroll
        for (int i = 0; i < 16; i++) {
            unsigned long long h2 = hb[(i << 3) | s];
            ffma2(a0, wp[0][i], h2);
            ffma2(a1, wp[1][i], h2);
            ffma2(a2, wp[2][i], h2);
        }
        float2 f;
        f = upk2(a0);  float v0 = f.x + f.y;
        f = upk2(a1);  float v1 = f.x + f.y;
        f = upk2(a2);  float v2 = f.x + f.y;
        #pragma unroll
        for (int d = 4; d >= 1; d >>= 1) {
            v0 += __shfl_xor_sync(0xffffffffu, v0, d, 8);
            v1 += __shfl_xor_sync(0xffffffffu, v1, d, 8);
            v2 += __shfl_xor_sync(0xffffffffu, v2, d, 8);
        }

        // gate math on ALL threads (bit-identical across s)
        float r = sigm(gis[t][jl]      + v0 + bh0);
        float z = sigm(gis[t][32 + jl] + v1 + bh1);
        float n = tanh_fast(gis[t][64 + jl] + r * (v2 + bh2));
        float hnew = n + z * (hpv - n);
        hpv = hnew;

        __syncthreads();   // orders thread0's expect post before our stores

        // one async store per thread: h[j] -> peer rank=s, buffer (t+1)%3
        uint32_t dst = smem_u32(&hs[(t + 1) % 3][fidx]);
        st_async_f32(dst, barT, s, hnew);

        mbar_wait_parity(barT, (t >> 1) & 1);
    }

    // ---- output head: final h (t=16) is in hs[16%3 = 1] of every CTA.
    {
        int ol = tid >> 4;           // 0..15
        int kq = tid & 15;           // 0..15
        int o  = rank * 16 + ol;
        const float* wo = Wout + (long long)o * HID;
        float a = 0.0f;
        #pragma unroll
        for (int m = 0; m < 16; m++) {
            int k    = kq * 16 + m;
            int pp   = k >> 1;
            int sl   = ((pp & 15) << 3) | (pp >> 4);
            a += wo[k] * hs[1][2 * sl + (k & 1)];
        }
        a += __shfl_down_sync(0xffffffffu, a, 8, 16);
        a += __shfl_down_sync(0xffffffffu, a, 4, 16);
        a += __shfl_down_sync(0xffffffffu, a, 2, 16);
        a += __shfl_down_sync(0xffffffffu, a, 1, 16);
        if (kq == 0) out[b * OUTSZ + o] = a + bout[o];
    }
}

// =====================================================================
extern "C" void kernel_launch(void* const* d_in, const int* in_sizes, int n_in,
                              void* d_out, int out_size) {
    const float* x    = (const float*)d_in[0];
    const float* Wih  = (const float*)d_in[1];
    const float* Whh  = (const float*)d_in[2];
    const float* bih  = (const float*)d_in[3];
    const float* bhh  = (const float*)d_in[4];
    const float* Wout = (const float*)d_in[5];
    const float* bout = (const float*)d_in[6];
    float* out = (float*)d_out;

    pool_kernel<<<1792, 256>>>(x);                 // 14336 warps
    gru_kernel<<<64, 256>>>(Wih, bih, Whh, bhh, Wout, bout, out);  // 8 clusters x 8 CTAs
}

// round 9
// speedup vs baseline: 1.2413x; 1.2413x over previous
#include <cuda_runtime.h>
#include <cstdint>

#define HID   256
#define BB    8
#define TT    16
#define INSZ  784
#define OUTSZ 128

// scratch (no device allocs allowed)
__device__ float g_seq[TT * BB * INSZ];       // [t][b][784]

typedef unsigned long long ull;

// ---------------- f32x2 helpers ----------------
__device__ __forceinline__ ull pk2(float a, float b) {
    ull r;
    asm("mov.b64 %0, {%1,%2};" : "=l"(r) : "f"(a), "f"(b));
    return r;
}
__device__ __forceinline__ float2 upk2(ull v) {
    float2 f;
    asm("mov.b64 {%0,%1}, %2;" : "=f"(f.x), "=f"(f.y) : "l"(v));
    return f;
}
__device__ __forceinline__ void ffma2(ull& d, ull a, ull b) {
    asm("fma.rn.f32x2 %0, %1, %2, %0;" : "+l"(d) : "l"(a), "l"(b));
}
__device__ __forceinline__ uint32_t smem_u32(const void* p) {
    uint32_t a;
    asm("{ .reg .u64 t; cvta.to.shared.u64 t, %1; cvt.u32.u64 %0, t; }"
        : "=r"(a) : "l"(p));
    return a;
}
__device__ __forceinline__ void cluster_sync_() {
    asm volatile("barrier.cluster.arrive.aligned;" ::: "memory");
    asm volatile("barrier.cluster.wait.aligned;"   ::: "memory");
}
__device__ __forceinline__ void st_async_f32(uint32_t dst_local, uint32_t bar_local,
                                             int rank, float v) {
    asm volatile(
        "{ .reg .b32 rd, rb;\n\t"
        "mapa.shared::cluster.u32 rd, %0, %2;\n\t"
        "mapa.shared::cluster.u32 rb, %1, %2;\n\t"
        "st.async.shared::cluster.mbarrier::complete_tx::bytes.f32 [rd], %3, [rb];\n\t"
        "}"
        :: "r"(dst_local), "r"(bar_local), "r"(rank), "f"(v) : "memory");
}
__device__ __forceinline__ void mbar_init(uint32_t bar, unsigned cnt) {
    asm volatile("mbarrier.init.shared.b64 [%0], %1;" :: "r"(bar), "r"(cnt) : "memory");
}
__device__ __forceinline__ void mbar_expect_tx(uint32_t bar, unsigned bytes) {
    asm volatile("mbarrier.arrive.expect_tx.shared.b64 _, [%0], %1;"
                 :: "r"(bar), "r"(bytes) : "memory");
}
__device__ __forceinline__ void mbar_wait_parity(uint32_t bar, unsigned parity) {
    asm volatile(
        "{ .reg .pred P;\n\t"
        "WL%=:\n\t"
        "mbarrier.try_wait.parity.acquire.cluster.shared::cta.b64 P, [%0], %1, 0x989680;\n\t"
        "@P bra WD%=;\n\t"
        "bra WL%=;\n\t"
        "WD%=:\n\t"
        "}"
        :: "r"(bar), "r"(parity) : "memory");
}
__device__ __forceinline__ float sigm(float x) {
    return 1.0f / (1.0f + __expf(-x));
}
__device__ __forceinline__ float tanh_fast(float x) {
    return 2.0f / (1.0f + __expf(-2.0f * x)) - 1.0f;
}

// =====================================================================
// Kernel 1: fused 3D+2D adaptive avg pool (proven, at DRAM roofline).
// =====================================================================
__global__ void pool_kernel(const float* __restrict__ x) {
    int gwarp = (blockIdx.x * blockDim.x + threadIdx.x) >> 5;
    int lane  = threadIdx.x & 31;

    int h2 = gwarp % 7;  int tmp = gwarp / 7;
    int d2 = tmp % 16;   tmp /= 16;
    int c  = tmp % 16;   tmp /= 16;
    int b  = tmp;        // 0..7

    const float* base = x + (((long long)(b * 16 + c) * 32 + d2 * 2) * 112
                             + h2 * 16) * 112;
    float acc0 = 0.0f, acc1 = 0.0f;
    if (lane < 28) {
        #pragma unroll
        for (int dd = 0; dd < 2; dd++) {
            #pragma unroll 8
            for (int hh = 0; hh < 16; hh += 2) {
                const float4* r0 = (const float4*)(base + dd * 12544 + hh * 112);
                const float4* r1 = (const float4*)(base + dd * 12544 + (hh + 1) * 112);
                float4 v0 = __ldcs(r0 + lane);
                float4 v1 = __ldcs(r1 + lane);
                acc0 += (v0.x + v0.y) + (v0.z + v0.w);
                acc1 += (v1.x + v1.y) + (v1.z + v1.w);
            }
        }
    }
    float acc = acc0 + acc1;
    acc += __shfl_down_sync(0xffffffffu, acc, 2);
    acc += __shfl_down_sync(0xffffffffu, acc, 1);
    if (lane < 28 && (lane & 3) == 0) {
        int w2 = lane >> 2;
        g_seq[(d2 * BB + b) * INSZ + c * 49 + h2 * 7 + w2] = acc * (1.0f / 512.0f);
    }
}

// =====================================================================
// Kernel 2: FUSED gi + GRU + head. One 8-CTA cluster per batch.
// Phase A (register-lean): thread (jl = tid>>3, s = tid&7) owns
//   rows j (3 gates) x t-pair {2s, 2s+1} x FULL k=784
// -> acc[3][2] f32x2 (12 regs), no reduction, direct gis writes.
// seq[b] staged in smem in 112-k double-buffered chunks (stride 120,
// 16B-aligned rows); Wih streamed as ulonglong2 (f32x2 pairs, no movs;
// 8 s-lanes share addresses -> broadcast-coalesced LDG.128).
// Phase B: R7-proven mbarrier ping-pong step loop + output head.
// =====================================================================
__global__ void __launch_bounds__(256, 1) __cluster_dims__(8, 1, 1)
gru_kernel(const float* __restrict__ Wih,
           const float* __restrict__ bih,
           const float* __restrict__ Whh,
           const float* __restrict__ bhh,
           const float* __restrict__ Wout,
           const float* __restrict__ bout,
           float* __restrict__ out) {
    __shared__ __align__(16) float seqS[2][TT][120];  // k-chunk double buffer
    __shared__ float hs[3][264];     // triple-buffered h (swizzled)
    __shared__ float gis[TT][96];    // gi[t][g*32+jl] for this (b, rank)
    __shared__ __align__(8) ull mbar[2];

    int tid  = threadIdx.x;
    int b    = blockIdx.x >> 3;      // batch = cluster id
    int rank = blockIdx.x & 7;       // cluster rank
    int jl   = tid >> 3;             // 0..31
    int s    = tid & 7;              // 0..7
    int j    = rank * 32 + jl;       // owned hidden unit

    uint32_t bar0 = smem_u32(&mbar[0]);
    uint32_t bar1 = smem_u32(&mbar[1]);
    for (int q = tid; q < 3 * 264; q += 256) (&hs[0][0])[q] = 0.0f;
    if (tid == 0) {
        mbar_init(bar0, 1);
        mbar_init(bar1, 1);
        mbar_expect_tx(bar0, 1024);
    }

    // ---------------- Phase A: gi slice ----------------
    int t0 = 2 * s, t1 = 2 * s + 1;
    float bia0 = bih[j], bia1 = bih[HID + j], bia2 = bih[2 * HID + j];

    const ulonglong2* Wq0 = (const ulonglong2*)(Wih + (long long)(0 * HID + j) * INSZ);
    const ulonglong2* Wq1 = (const ulonglong2*)(Wih + (long long)(1 * HID + j) * INSZ);
    const ulonglong2* Wq2 = (const ulonglong2*)(Wih + (long long)(2 * HID + j) * INSZ);

    ull a00 = 0, a01 = 0, a10 = 0, a11 = 0, a20 = 0, a21 = 0;

    // preload chunk 0 (16 t x 112 k = 896 float2)
    {
        #pragma unroll
        for (int m = 0; m < 4; m++) {
            int i = tid + 256 * m;
            if (i < 896) {
                int r = i / 56, c2 = i % 56;
                *(float2*)&seqS[0][r][2 * c2] =
                    *(const float2*)(g_seq + (r * BB + b) * INSZ + 2 * c2);
            }
        }
    }
    __syncthreads();

    for (int kc = 0; kc < 7; kc++) {
        int cur = kc & 1;
        float2 rf[4];
        if (kc < 6) {
            int k0 = (kc + 1) * 112;
            #pragma unroll
            for (int m = 0; m < 4; m++) {
                int i = tid + 256 * m;
                if (i < 896) {
                    int r = i / 56, c2 = i % 56;
                    rf[m] = *(const float2*)(g_seq + (r * BB + b) * INSZ + k0 + 2 * c2);
                }
            }
        }
        const ulonglong2* s0r = (const ulonglong2*)&seqS[cur][t0][0];
        const ulonglong2* s1r = (const ulonglong2*)&seqS[cur][t1][0];
        int qoff = kc * 28;
        #pragma unroll 14
        for (int q = 0; q < 28; q++) {
            ulonglong2 w0 = Wq0[qoff + q];
            ulonglong2 w1 = Wq1[qoff + q];
            ulonglong2 w2 = Wq2[qoff + q];
            ulonglong2 sa = s0r[q];
            ulonglong2 sb = s1r[q];
            ffma2(a00, w0.x, sa.x);  ffma2(a00, w0.y, sa.y);
            ffma2(a01, w0.x, sb.x);  ffma2(a01, w0.y, sb.y);
            ffma2(a10, w1.x, sa.x);  ffma2(a10, w1.y, sa.y);
            ffma2(a11, w1.x, sb.x);  ffma2(a11, w1.y, sb.y);
            ffma2(a20, w2.x, sa.x);  ffma2(a20, w2.y, sa.y);
            ffma2(a21, w2.x, sb.x);  ffma2(a21, w2.y, sb.y);
        }
        if (kc < 6) {
            int nxt = cur ^ 1;
            #pragma unroll
            for (int m = 0; m < 4; m++) {
                int i = tid + 256 * m;
                if (i < 896) {
                    int r = i / 56, c2 = i % 56;
                    *(float2*)&seqS[nxt][r][2 * c2] = rf[m];
                }
            }
        }
        __syncthreads();
    }
    {
        float2 f;
        f = upk2(a00);  gis[t0][jl]          = f.x + f.y + bia0;
        f = upk2(a01);  gis[t1][jl]          = f.x + f.y + bia0;
        f = upk2(a10);  gis[t0][32 + jl]     = f.x + f.y + bia1;
        f = upk2(a11);  gis[t1][32 + jl]     = f.x + f.y + bia1;
        f = upk2(a20);  gis[t0][64 + jl]     = f.x + f.y + bia2;
        f = upk2(a21);  gis[t1][64 + jl]     = f.x + f.y + bia2;
    }

    // ---------------- W_hh slice into registers ----------------
    ull wp[3][16];
    #pragma unroll
    for (int g = 0; g < 3; g++) {
        const ulonglong2* ws =
            (const ulonglong2*)(Whh + (long long)(g * HID + j) * HID + s * 32);
        #pragma unroll
        for (int m = 0; m < 8; m++) {
            ulonglong2 v = ws[m];
            wp[g][2 * m]     = v.x;
            wp[g][2 * m + 1] = v.y;
        }
    }
    float bh0 = bhh[j], bh1 = bhh[HID + j], bh2 = bhh[2 * HID + j];

    __syncthreads();
    cluster_sync_();                      // gis ready, barriers inited everywhere

    // swizzled float index for my j (store target in peer buffers)
    int p_    = j >> 1;
    int slot_ = ((p_ & 15) << 3) | (p_ >> 4);
    int fidx  = 2 * slot_ + (j & 1);

    float hpv = 0.0f;                     // hprev for (b, j): all s identical

    for (int t = 0; t < TT; t++) {
        uint32_t barT = (t & 1) ? bar1 : bar0;
        if (tid == 0 && t < TT - 1)
            mbar_expect_tx((t & 1) ? bar0 : bar1, 1024);   // for step t+1

        const ull* hb = (const ull*)hs[t % 3];

        ull d0 = 0, d1 = 0, d2 = 0;
        #pragma unroll
        for (int i = 0; i < 16; i++) {
            ull h2 = hb[(i << 3) | s];
            ffma2(d0, wp[0][i], h2);
            ffma2(d1, wp[1][i], h2);
            ffma2(d2, wp[2][i], h2);
        }
        float2 f;
        f = upk2(d0);  float v0 = f.x + f.y;
        f = upk2(d1);  float v1 = f.x + f.y;
        f = upk2(d2);  float v2 = f.x + f.y;
        #pragma unroll
        for (int d = 4; d >= 1; d >>= 1) {
            v0 += __shfl_xor_sync(0xffffffffu, v0, d, 8);
            v1 += __shfl_xor_sync(0xffffffffu, v1, d, 8);
            v2 += __shfl_xor_sync(0xffffffffu, v2, d, 8);
        }

        float r = sigm(gis[t][jl]      + v0 + bh0);
        float z = sigm(gis[t][32 + jl] + v1 + bh1);
        float n = tanh_fast(gis[t][64 + jl] + r * (v2 + bh2));
        float hnew = n + z * (hpv - n);
        hpv = hnew;

        __syncthreads();   // orders thread0's expect post before our stores

        uint32_t dst = smem_u32(&hs[(t + 1) % 3][fidx]);
        st_async_f32(dst, barT, s, hnew);

        mbar_wait_parity(barT, (t >> 1) & 1);
    }

    // ---- output head: final h (t=16) is in hs[16%3 = 1] of every CTA.
    {
        int ol = tid >> 4;           // 0..15
        int kq = tid & 15;           // 0..15
        int o  = rank * 16 + ol;
        const float* wo = Wout + (long long)o * HID;
        float a = 0.0f;
        #pragma unroll
        for (int m = 0; m < 16; m++) {
            int k    = kq * 16 + m;
            int pp   = k >> 1;
            int sl   = ((pp & 15) << 3) | (pp >> 4);
            a += wo[k] * hs[1][2 * sl + (k & 1)];
        }
        a += __shfl_down_sync(0xffffffffu, a, 8, 16);
        a += __shfl_down_sync(0xffffffffu, a, 4, 16);
        a += __shfl_down_sync(0xffffffffu, a, 2, 16);
        a += __shfl_down_sync(0xffffffffu, a, 1, 16);
        if (kq == 0) out[b * OUTSZ + o] = a + bout[o];
    }
}

// =====================================================================
extern "C" void kernel_launch(void* const* d_in, const int* in_sizes, int n_in,
                              void* d_out, int out_size) {
    const float* x    = (const float*)d_in[0];
    const float* Wih  = (const float*)d_in[1];
    const float* Whh  = (const float*)d_in[2];
    const float* bih  = (const float*)d_in[3];
    const float* bhh  = (const float*)d_in[4];
    const float* Wout = (const float*)d_in[5];
    const float* bout = (const float*)d_in[6];
    float* out = (float*)d_out;

    pool_kernel<<<1792, 256>>>(x);                 // 14336 warps
    gru_kernel<<<64, 256>>>(Wih, bih, Whh, bhh, Wout, bout, out);  // 8 clusters x 8 CTAs
}

// round 10
// speedup vs baseline: 1.5144x; 1.2200x over previous
#include <cuda_runtime.h>
#include <cstdint>

#define HID   256
#define BB    8
#define TT    16
#define INSZ  784
#define OUTSZ 128

// scratch (no device allocs allowed)
__device__ float g_seq[TT * BB * INSZ];       // [t][b][784]
__device__ float g_gi [TT * BB * 3 * HID];    // [t][b][768]

typedef unsigned long long ull;

// ---------------- f32x2 helpers ----------------
__device__ __forceinline__ ull pk2(float a, float b) {
    ull r;
    asm("mov.b64 %0, {%1,%2};" : "=l"(r) : "f"(a), "f"(b));
    return r;
}
__device__ __forceinline__ float2 upk2(ull v) {
    float2 f;
    asm("mov.b64 {%0,%1}, %2;" : "=f"(f.x), "=f"(f.y) : "l"(v));
    return f;
}
__device__ __forceinline__ void ffma2(ull& d, ull a, ull b) {
    asm("fma.rn.f32x2 %0, %1, %2, %0;" : "+l"(d) : "l"(a), "l"(b));
}
__device__ __forceinline__ uint32_t smem_u32(const void* p) {
    uint32_t a;
    asm("{ .reg .u64 t; cvta.to.shared.u64 t, %1; cvt.u32.u64 %0, t; }"
        : "=r"(a) : "l"(p));
    return a;
}
__device__ __forceinline__ void cluster_sync_() {
    asm volatile("barrier.cluster.arrive.aligned;" ::: "memory");
    asm volatile("barrier.cluster.wait.aligned;"   ::: "memory");
}
// async remote b64 store with tx-completion on target CTA's mbarrier
__device__ __forceinline__ void st_async_b64(uint32_t dst_local, uint32_t bar_local,
                                             int rank, ull v) {
    asm volatile(
        "{ .reg .b32 rd, rb;\n\t"
        "mapa.shared::cluster.u32 rd, %0, %2;\n\t"
        "mapa.shared::cluster.u32 rb, %1, %2;\n\t"
        "st.async.shared::cluster.mbarrier::complete_tx::bytes.b64 [rd], %3, [rb];\n\t"
        "}"
        :: "r"(dst_local), "r"(bar_local), "r"(rank), "l"(v) : "memory");
}
__device__ __forceinline__ void mbar_init(uint32_t bar, unsigned cnt) {
    asm volatile("mbarrier.init.shared.b64 [%0], %1;" :: "r"(bar), "r"(cnt) : "memory");
}
__device__ __forceinline__ void mbar_expect_tx(uint32_t bar, unsigned bytes) {
    asm volatile("mbarrier.arrive.expect_tx.shared.b64 _, [%0], %1;"
                 :: "r"(bar), "r"(bytes) : "memory");
}
__device__ __forceinline__ void mbar_wait_parity(uint32_t bar, unsigned parity) {
    asm volatile(
        "{ .reg .pred P;\n\t"
        "WL%=:\n\t"
        "mbarrier.try_wait.parity.acquire.cluster.shared::cta.b64 P, [%0], %1, 0x989680;\n\t"
        "@P bra WD%=;\n\t"
        "bra WL%=;\n\t"
        "WD%=:\n\t"
        "}"
        :: "r"(bar), "r"(parity) : "memory");
}
__device__ __forceinline__ float sigm(float x) {
    return 1.0f / (1.0f + __expf(-x));
}
__device__ __forceinline__ float tanh_fast(float x) {
    return 2.0f / (1.0f + __expf(-2.0f * x)) - 1.0f;
}

// =====================================================================
// Kernel 1: fused 3D+2D adaptive avg pool, ALIGNED row-pair reads.
// One warp per (b,c,d2,h2). Each (dd, row-pair pp) is 224 contiguous
// floats = 896B, 128B-aligned (base offsets are multiples of 128B).
// load1: lanes 0..31 -> float4 #l; load2: lanes 0..23 -> float4 #(l+32).
// Static lane->bin map; shuffle recombine (derivation in commit msg).
// =====================================================================
__global__ void pool_kernel(const float* __restrict__ x) {
    int gwarp = (blockIdx.x * blockDim.x + threadIdx.x) >> 5;
    int lane  = threadIdx.x & 31;

    int h2 = gwarp % 7;  int tmp = gwarp / 7;
    int d2 = tmp % 16;   tmp /= 16;
    int c  = tmp % 16;   tmp /= 16;
    int b  = tmp;        // 0..7

    const float* base = x + ((long long)(b * 16 + c) * 32 + d2 * 2) * 12544
                          + h2 * 1792;

    float acc_a = 0.0f, acc_b = 0.0f;
    #pragma unroll
    for (int dd = 0; dd < 2; dd++) {
        #pragma unroll
        for (int pp = 0; pp < 8; pp++) {        // 8 row-pairs of 224 floats
            const float4* p4 = (const float4*)(base + dd * 12544 + pp * 224);
            float4 va = __ldcs(p4 + lane);
            acc_a += (va.x + va.y) + (va.z + va.w);
            if (lane < 24) {
                float4 vb = __ldcs(p4 + lane + 32);
                acc_b += (vb.x + vb.y) + (vb.z + vb.w);
            }
        }
    }
    // recombine: v(l) = acc_a(l) + [l>=4 ? acc_b(l-4) : acc_a(l+28)]
    float t1 = __shfl_up_sync(0xffffffffu, acc_b, 4);
    float t2 = __shfl_down_sync(0xffffffffu, acc_a, 28);
    float tot = acc_a + ((lane >= 4) ? t1 : t2);
    tot += __shfl_down_sync(0xffffffffu, tot, 2);
    tot += __shfl_down_sync(0xffffffffu, tot, 1);
    if (lane < 28 && (lane & 3) == 0) {
        int w2 = lane >> 2;
        g_seq[(d2 * BB + b) * INSZ + c * 49 + h2 * 7 + w2] = tot * (1.0f / 512.0f);
    }
}

// =====================================================================
// Kernel 2: gi = seq @ W_ih^T + b_ih (R6/R7-proven double-buffered).
// =====================================================================
__global__ void gi_kernel(const float* __restrict__ Wih,
                          const float* __restrict__ bih) {
    __shared__ __align__(16) float Ash[2][32][58];
    __shared__ __align__(16) float Bsh[2][32][58];

    int tid = threadIdx.x;
    int g0  = blockIdx.x * 32;
    int tb0 = blockIdx.y * 32;
    int tb  = tid & 31;
    int wid = tid >> 5;               // 0..7

    #pragma unroll
    for (int m = 0; m < 7; m++) {
        int i = tid + 256 * m;
        int r = i / 56, k = i % 56;
        Ash[0][r][k] = g_seq[(tb0 + r) * INSZ + k];
        Bsh[0][r][k] = Wih[(long long)(g0 + r) * INSZ + k];
    }
    __syncthreads();

    ull acc[4] = {0ull, 0ull, 0ull, 0ull};
    float ra[7], rb[7];

    for (int it = 0; it < 14; it++) {
        int cur = it & 1, nxt = cur ^ 1;
        if (it < 13) {
            int k0 = (it + 1) * 56;
            #pragma unroll
            for (int m = 0; m < 7; m++) {
                int i = tid + 256 * m;
                int r = i / 56, k = i % 56;
                ra[m] = g_seq[(tb0 + r) * INSZ + k0 + k];
                rb[m] = Wih[(long long)(g0 + r) * INSZ + k0 + k];
            }
        }
        const ull* Ar = (const ull*)Ash[cur][tb];
        const ull* B0 = (const ull*)Bsh[cur][wid];
        const ull* B1 = (const ull*)Bsh[cur][wid + 8];
        const ull* B2 = (const ull*)Bsh[cur][wid + 16];
        const ull* B3 = (const ull*)Bsh[cur][wid + 24];
        #pragma unroll
        for (int kk = 0; kk < 28; kk++) {
            ull a2 = Ar[kk];
            ffma2(acc[0], a2, B0[kk]);
            ffma2(acc[1], a2, B1[kk]);
            ffma2(acc[2], a2, B2[kk]);
            ffma2(acc[3], a2, B3[kk]);
        }
        if (it < 13) {
            #pragma unroll
            for (int m = 0; m < 7; m++) {
                int i = tid + 256 * m;
                int r = i / 56, k = i % 56;
                Ash[nxt][r][k] = ra[m];
                Bsh[nxt][r][k] = rb[m];
            }
        }
        __syncthreads();
    }
    #pragma unroll
    for (int i = 0; i < 4; i++) {
        int g = g0 + wid + 8 * i;
        float2 f = upk2(acc[i]);
        g_gi[(tb0 + tb) * (3 * HID) + g] = f.x + f.y + bih[g];
    }
}

// =====================================================================
// Kernel 3: GRU, one 8-CTA cluster PER BATCH (R7-proven protocol),
// now with PAIRED b64 st.async (128 arrivals/step instead of 256).
// =====================================================================
__global__ void __launch_bounds__(256, 1) __cluster_dims__(8, 1, 1)
gru_kernel(const float* __restrict__ Whh,
           const float* __restrict__ bhh,
           const float* __restrict__ Wout,
           const float* __restrict__ bout,
           float* __restrict__ out) {
    __shared__ float hs[3][264];     // triple-buffered h (swizzled)
    __shared__ float gis[TT][96];    // gi[t][g*32+jl] for this (b, rank)
    __shared__ __align__(8) ull mbar[2];

    int tid  = threadIdx.x;
    int b    = blockIdx.x >> 3;      // batch = cluster id
    int rank = blockIdx.x & 7;       // cluster rank
    int jl   = tid >> 3;             // 0..31
    int s    = tid & 7;              // 0..7
    int j    = rank * 32 + jl;       // owned hidden unit

    // --- W_hh slice into registers: gate g, k = s*32 .. s*32+31 ---
    ull wp[3][16];
    #pragma unroll
    for (int g = 0; g < 3; g++) {
        const ulonglong2* ws =
            (const ulonglong2*)(Whh + (long long)(g * HID + j) * HID + s * 32);
        #pragma unroll
        for (int m = 0; m < 8; m++) {
            ulonglong2 v = ws[m];
            wp[g][2 * m]     = v.x;
            wp[g][2 * m + 1] = v.y;
        }
    }
    float bh0 = bhh[j], bh1 = bhh[HID + j], bh2 = bhh[2 * HID + j];

    // --- preload gi slice ---
    #pragma unroll
    for (int i = tid; i < TT * 96; i += 256) {
        int t = i / 96, r = i % 96;
        int g = r >> 5, jj = r & 31;
        gis[t][r] = g_gi[(long long)(t * BB + b) * (3 * HID) + g * HID + rank * 32 + jj];
    }
    // zero all 3 h buffers
    for (int q = tid; q < 3 * 264; q += 256) (&hs[0][0])[q] = 0.0f;

    uint32_t bar0 = smem_u32(&mbar[0]);
    uint32_t bar1 = smem_u32(&mbar[1]);
    if (tid == 0) {
        mbar_init(bar0, 1);
        mbar_init(bar1, 1);
        mbar_expect_tx(bar0, 1024);       // for step 0's stores
    }
    __syncthreads();
    cluster_sync_();                      // all barriers inited, buffers zeroed

    // swizzled b64 slot for my pair (j even): pair p = j>>1
    // (fidx computed for even-jl threads; they store (h_j, h_j+1))
    int p_    = (rank * 32 + (jl & ~1)) >> 1;
    int slot_ = ((p_ & 15) << 3) | (p_ >> 4);

    float hpv = 0.0f;                     // hprev for (b, j): all s identical

    for (int t = 0; t < TT; t++) {
        uint32_t barT = (t & 1) ? bar1 : bar0;
        if (tid == 0 && t < TT - 1)
            mbar_expect_tx((t & 1) ? bar0 : bar1, 1024);   // for step t+1

        const ull* hb = (const ull*)hs[t % 3];

        ull d0 = 0, d1 = 0, d2 = 0;
        #pragma unroll
        for (int i = 0; i < 16; i++) {
            ull h2 = hb[(i << 3) | s];
            ffma2(d0, wp[0][i], h2);
            ffma2(d1, wp[1][i], h2);
            ffma2(d2, wp[2][i], h2);
        }
        float2 f;
        f = upk2(d0);  float v0 = f.x + f.y;
        f = upk2(d1);  float v1 = f.x + f.y;
        f = upk2(d2);  float v2 = f.x + f.y;
        #pragma unroll
        for (int d = 4; d >= 1; d >>= 1) {
            v0 += __shfl_xor_sync(0xffffffffu, v0, d, 8);
            v1 += __shfl_xor_sync(0xffffffffu, v1, d, 8);
            v2 += __shfl_xor_sync(0xffffffffu, v2, d, 8);
        }

        // gate math on ALL threads (bit-identical across s)
        float r = sigm(gis[t][jl]      + v0 + bh0);
        float z = sigm(gis[t][32 + jl] + v1 + bh1);
        float n = tanh_fast(gis[t][64 + jl] + r * (v2 + bh2));
        float hnew = n + z * (hpv - n);
        hpv = hnew;

        // partner hnew (jl+1, same s) lives at lane+8 in this warp
        float hn1 = __shfl_down_sync(0xffffffffu, hnew, 8);

        __syncthreads();   // orders thread0's expect post before our stores

        if ((jl & 1) == 0) {
            ull pair = pk2(hnew, hn1);
            uint32_t dst = smem_u32((const char*)&hs[(t + 1) % 3][0] + 8 * slot_);
            st_async_b64(dst, barT, s, pair);
        }

        mbar_wait_parity(barT, (t >> 1) & 1);
    }

    // ---- output head: final h (t=16) is in hs[16%3 = 1] of every CTA.
    {
        int ol = tid >> 4;           // 0..15
        int kq = tid & 15;           // 0..15
        int o  = rank * 16 + ol;
        const float* wo = Wout + (long long)o * HID;
        float a = 0.0f;
        #pragma unroll
        for (int m = 0; m < 16; m++) {
            int k    = kq * 16 + m;
            int pp   = k >> 1;
            int sl   = ((pp & 15) << 3) | (pp >> 4);
            a += wo[k] * hs[1][2 * sl + (k & 1)];
        }
        a += __shfl_down_sync(0xffffffffu, a, 8, 16);
        a += __shfl_down_sync(0xffffffffu, a, 4, 16);
        a += __shfl_down_sync(0xffffffffu, a, 2, 16);
        a += __shfl_down_sync(0xffffffffu, a, 1, 16);
        if (kq == 0) out[b * OUTSZ + o] = a + bout[o];
    }
}

// =====================================================================
extern "C" void kernel_launch(void* const* d_in, const int* in_sizes, int n_in,
                              void* d_out, int out_size) {
    const float* x    = (const float*)d_in[0];
    const float* Wih  = (const float*)d_in[1];
    const float* Whh  = (const float*)d_in[2];
    const float* bih  = (const float*)d_in[3];
    const float* bhh  = (const float*)d_in[4];
    const float* Wout = (const float*)d_in[5];
    const float* bout = (const float*)d_in[6];
    float* out = (float*)d_out;

    pool_kernel<<<1792, 256>>>(x);                 // 14336 warps
    gi_kernel<<<dim3(24, 4), 256>>>(Wih, bih);
    gru_kernel<<<64, 256>>>(Whh, bhh, Wout, bout, out);   // 8 clusters x 8 CTAs
}

// round 11
// speedup vs baseline: 1.5627x; 1.0319x over previous
#include <cuda_runtime.h>
#include <cstdint>

#define HID   256
#define BB    8
#define TT    16
#define INSZ  784
#define OUTSZ 128

// scratch (no device allocs allowed)
__device__ float g_seq[TT * BB * INSZ];       // [t][b][784]
__device__ float g_giA[TT * BB * 3 * HID];    // k-half 0 partial (+bias)
__device__ float g_giB[TT * BB * 3 * HID];    // k-half 1 partial

typedef unsigned long long ull;

// ---------------- f32x2 helpers ----------------
__device__ __forceinline__ ull pk2(float a, float b) {
    ull r;
    asm("mov.b64 %0, {%1,%2};" : "=l"(r) : "f"(a), "f"(b));
    return r;
}
__device__ __forceinline__ float2 upk2(ull v) {
    float2 f;
    asm("mov.b64 {%0,%1}, %2;" : "=f"(f.x), "=f"(f.y) : "l"(v));
    return f;
}
__device__ __forceinline__ void ffma2(ull& d, ull a, ull b) {
    asm("fma.rn.f32x2 %0, %1, %2, %0;" : "+l"(d) : "l"(a), "l"(b));
}
__device__ __forceinline__ uint32_t smem_u32(const void* p) {
    uint32_t a;
    asm("{ .reg .u64 t; cvta.to.shared.u64 t, %1; cvt.u32.u64 %0, t; }"
        : "=r"(a) : "l"(p));
    return a;
}
__device__ __forceinline__ void cluster_sync_() {
    asm volatile("barrier.cluster.arrive.aligned;" ::: "memory");
    asm volatile("barrier.cluster.wait.aligned;"   ::: "memory");
}
// async remote b64 store with tx-completion on target CTA's mbarrier
__device__ __forceinline__ void st_async_b64(uint32_t dst_local, uint32_t bar_local,
                                             int rank, ull v) {
    asm volatile(
        "{ .reg .b32 rd, rb;\n\t"
        "mapa.shared::cluster.u32 rd, %0, %2;\n\t"
        "mapa.shared::cluster.u32 rb, %1, %2;\n\t"
        "st.async.shared::cluster.mbarrier::complete_tx::bytes.b64 [rd], %3, [rb];\n\t"
        "}"
        :: "r"(dst_local), "r"(bar_local), "r"(rank), "l"(v) : "memory");
}
__device__ __forceinline__ void mbar_init(uint32_t bar, unsigned cnt) {
    asm volatile("mbarrier.init.shared.b64 [%0], %1;" :: "r"(bar), "r"(cnt) : "memory");
}
__device__ __forceinline__ void mbar_expect_tx(uint32_t bar, unsigned bytes) {
    asm volatile("mbarrier.arrive.expect_tx.shared.b64 _, [%0], %1;"
                 :: "r"(bar), "r"(bytes) : "memory");
}
__device__ __forceinline__ void mbar_wait_parity(uint32_t bar, unsigned parity) {
    asm volatile(
        "{ .reg .pred P;\n\t"
        "WL%=:\n\t"
        "mbarrier.try_wait.parity.acquire.cluster.shared::cta.b64 P, [%0], %1, 0x989680;\n\t"
        "@P bra WD%=;\n\t"
        "bra WL%=;\n\t"
        "WD%=:\n\t"
        "}"
        :: "r"(bar), "r"(parity) : "memory");
}
__device__ __forceinline__ float sigm(float x) {
    return 1.0f / (1.0f + __expf(-x));
}
__device__ __forceinline__ float tanh_fast(float x) {
    return 2.0f / (1.0f + __expf(-2.0f * x)) - 1.0f;
}

// =====================================================================
// Kernel 1: fused 3D+2D adaptive avg pool, aligned row-pair reads
// (proven; pool is at the DRAM/LTS knee, 6.3 TB/s).
// =====================================================================
__global__ void pool_kernel(const float* __restrict__ x) {
    int gwarp = (blockIdx.x * blockDim.x + threadIdx.x) >> 5;
    int lane  = threadIdx.x & 31;

    int h2 = gwarp % 7;  int tmp = gwarp / 7;
    int d2 = tmp % 16;   tmp /= 16;
    int c  = tmp % 16;   tmp /= 16;
    int b  = tmp;        // 0..7

    const float* base = x + ((long long)(b * 16 + c) * 32 + d2 * 2) * 12544
                          + h2 * 1792;

    float acc_a = 0.0f, acc_b = 0.0f;
    #pragma unroll
    for (int dd = 0; dd < 2; dd++) {
        #pragma unroll
        for (int pp = 0; pp < 8; pp++) {        // 8 row-pairs of 224 floats
            const float4* p4 = (const float4*)(base + dd * 12544 + pp * 224);
            float4 va = __ldcs(p4 + lane);
            acc_a += (va.x + va.y) + (va.z + va.w);
            if (lane < 24) {
                float4 vb = __ldcs(p4 + lane + 32);
                acc_b += (vb.x + vb.y) + (vb.z + vb.w);
            }
        }
    }
    float t1 = __shfl_up_sync(0xffffffffu, acc_b, 4);
    float t2 = __shfl_down_sync(0xffffffffu, acc_a, 28);
    float tot = acc_a + ((lane >= 4) ? t1 : t2);
    tot += __shfl_down_sync(0xffffffffu, tot, 2);
    tot += __shfl_down_sync(0xffffffffu, tot, 1);
    if (lane < 28 && (lane & 3) == 0) {
        int w2 = lane >> 2;
        g_seq[(d2 * BB + b) * INSZ + c * 49 + h2 * 7 + w2] = tot * (1.0f / 512.0f);
    }
}

// =====================================================================
// Kernel 2: gi partials, SPLIT-K (2 halves of 392 = 7 x 56).
// grid (24, 4, 2); z = k-half. Half 0 adds bias -> g_giA, half 1 -> g_giB.
// GRU preload sums the two. Same double-buffered structure as proven.
// =====================================================================
__global__ void gi_kernel(const float* __restrict__ Wih,
                          const float* __restrict__ bih) {
    __shared__ __align__(16) float Ash[2][32][58];
    __shared__ __align__(16) float Bsh[2][32][58];

    int tid = threadIdx.x;
    int g0  = blockIdx.x * 32;
    int tb0 = blockIdx.y * 32;
    int kh  = blockIdx.z;             // 0 or 1
    int kb  = kh * 392;
    int tb  = tid & 31;
    int wid = tid >> 5;               // 0..7

    #pragma unroll
    for (int m = 0; m < 7; m++) {
        int i = tid + 256 * m;
        int r = i / 56, k = i % 56;
        Ash[0][r][k] = g_seq[(tb0 + r) * INSZ + kb + k];
        Bsh[0][r][k] = Wih[(long long)(g0 + r) * INSZ + kb + k];
    }
    __syncthreads();

    ull acc[4] = {0ull, 0ull, 0ull, 0ull};
    float ra[7], rb[7];

    for (int it = 0; it < 7; it++) {
        int cur = it & 1, nxt = cur ^ 1;
        if (it < 6) {
            int k0 = kb + (it + 1) * 56;
            #pragma unroll
            for (int m = 0; m < 7; m++) {
                int i = tid + 256 * m;
                int r = i / 56, k = i % 56;
                ra[m] = g_seq[(tb0 + r) * INSZ + k0 + k];
                rb[m] = Wih[(long long)(g0 + r) * INSZ + k0 + k];
            }
        }
        const ull* Ar = (const ull*)Ash[cur][tb];
        const ull* B0 = (const ull*)Bsh[cur][wid];
        const ull* B1 = (const ull*)Bsh[cur][wid + 8];
        const ull* B2 = (const ull*)Bsh[cur][wid + 16];
        const ull* B3 = (const ull*)Bsh[cur][wid + 24];
        #pragma unroll
        for (int kk = 0; kk < 28; kk++) {
            ull a2 = Ar[kk];
            ffma2(acc[0], a2, B0[kk]);
            ffma2(acc[1], a2, B1[kk]);
            ffma2(acc[2], a2, B2[kk]);
            ffma2(acc[3], a2, B3[kk]);
        }
        if (it < 6) {
            #pragma unroll
            for (int m = 0; m < 7; m++) {
                int i = tid + 256 * m;
                int r = i / 56, k = i % 56;
                Ash[nxt][r][k] = ra[m];
                Bsh[nxt][r][k] = rb[m];
            }
        }
        __syncthreads();
    }
    float* dst = (kh == 0) ? g_giA : g_giB;
    #pragma unroll
    for (int i = 0; i < 4; i++) {
        int g = g0 + wid + 8 * i;
        float2 f = upk2(acc[i]);
        float bias = (kh == 0) ? bih[g] : 0.0f;
        dst[(tb0 + tb) * (3 * HID) + g] = f.x + f.y + bias;
    }
}

// =====================================================================
// Kernel 3: GRU, one 8-CTA cluster PER BATCH (proven protocol; paired
// b64 st.async, mbarrier ping-pong, triple-buffered h).
// gis preload now sums the two split-K partials.
// =====================================================================
__global__ void __launch_bounds__(256, 1) __cluster_dims__(8, 1, 1)
gru_kernel(const float* __restrict__ Whh,
           const float* __restrict__ bhh,
           const float* __restrict__ Wout,
           const float* __restrict__ bout,
           float* __restrict__ out) {
    __shared__ float hs[3][264];     // triple-buffered h (swizzled)
    __shared__ float gis[TT][96];    // gi[t][g*32+jl] for this (b, rank)
    __shared__ __align__(8) ull mbar[2];

    int tid  = threadIdx.x;
    int b    = blockIdx.x >> 3;      // batch = cluster id
    int rank = blockIdx.x & 7;       // cluster rank
    int jl   = tid >> 3;             // 0..31
    int s    = tid & 7;              // 0..7
    int j    = rank * 32 + jl;       // owned hidden unit

    // --- W_hh slice into registers: gate g, k = s*32 .. s*32+31 ---
    ull wp[3][16];
    #pragma unroll
    for (int g = 0; g < 3; g++) {
        const ulonglong2* ws =
            (const ulonglong2*)(Whh + (long long)(g * HID + j) * HID + s * 32);
        #pragma unroll
        for (int m = 0; m < 8; m++) {
            ulonglong2 v = ws[m];
            wp[g][2 * m]     = v.x;
            wp[g][2 * m + 1] = v.y;
        }
    }
    float bh0 = bhh[j], bh1 = bhh[HID + j], bh2 = bhh[2 * HID + j];

    // --- preload gi slice = sum of split-K partials ---
    #pragma unroll
    for (int i = tid; i < TT * 96; i += 256) {
        int t = i / 96, r = i % 96;
        int g = r >> 5, jj = r & 31;
        long long idx = (long long)(t * BB + b) * (3 * HID) + g * HID + rank * 32 + jj;
        gis[t][r] = g_giA[idx] + g_giB[idx];
    }
    // zero all 3 h buffers
    for (int q = tid; q < 3 * 264; q += 256) (&hs[0][0])[q] = 0.0f;

    uint32_t bar0 = smem_u32(&mbar[0]);
    uint32_t bar1 = smem_u32(&mbar[1]);
    if (tid == 0) {
        mbar_init(bar0, 1);
        mbar_init(bar1, 1);
        mbar_expect_tx(bar0, 1024);       // for step 0's stores
    }
    __syncthreads();
    cluster_sync_();                      // all barriers inited, buffers zeroed

    // swizzled b64 slot for my pair (even jl): pair p = j>>1
    int p_    = (rank * 32 + (jl & ~1)) >> 1;
    int slot_ = ((p_ & 15) << 3) | (p_ >> 4);

    float hpv = 0.0f;                     // hprev for (b, j): all s identical

    for (int t = 0; t < TT; t++) {
        uint32_t barT = (t & 1) ? bar1 : bar0;
        if (tid == 0 && t < TT - 1)
            mbar_expect_tx((t & 1) ? bar0 : bar1, 1024);   // for step t+1

        const ull* hb = (const ull*)hs[t % 3];

        ull d0 = 0, d1 = 0, d2 = 0;
        #pragma unroll
        for (int i = 0; i < 16; i++) {
            ull h2 = hb[(i << 3) | s];
            ffma2(d0, wp[0][i], h2);
            ffma2(d1, wp[1][i], h2);
            ffma2(d2, wp[2][i], h2);
        }
        float2 f;
        f = upk2(d0);  float v0 = f.x + f.y;
        f = upk2(d1);  float v1 = f.x + f.y;
        f = upk2(d2);  float v2 = f.x + f.y;
        #pragma unroll
        for (int d = 4; d >= 1; d >>= 1) {
            v0 += __shfl_xor_sync(0xffffffffu, v0, d, 8);
            v1 += __shfl_xor_sync(0xffffffffu, v1, d, 8);
            v2 += __shfl_xor_sync(0xffffffffu, v2, d, 8);
        }

        // gate math on ALL threads (bit-identical across s)
        float r = sigm(gis[t][jl]      + v0 + bh0);
        float z = sigm(gis[t][32 + jl] + v1 + bh1);
        float n = tanh_fast(gis[t][64 + jl] + r * (v2 + bh2));
        float hnew = n + z * (hpv - n);
        hpv = hnew;

        // partner hnew (jl+1, same s) lives at lane+8 in this warp
        float hn1 = __shfl_down_sync(0xffffffffu, hnew, 8);

        __syncthreads();   // orders thread0's expect post before our stores

        if ((jl & 1) == 0) {
            ull pair = pk2(hnew, hn1);
            uint32_t dst = smem_u32((const char*)&hs[(t + 1) % 3][0] + 8 * slot_);
            st_async_b64(dst, barT, s, pair);
        }

        mbar_wait_parity(barT, (t >> 1) & 1);
    }

    // ---- output head: final h (t=16) is in hs[16%3 = 1] of every CTA.
    {
        int ol = tid >> 4;           // 0..15
        int kq = tid & 15;           // 0..15
        int o  = rank * 16 + ol;
        const float* wo = Wout + (long long)o * HID;
        float a = 0.0f;
        #pragma unroll
        for (int m = 0; m < 16; m++) {
            int k    = kq * 16 + m;
            int pp   = k >> 1;
            int sl   = ((pp & 15) << 3) | (pp >> 4);
            a += wo[k] * hs[1][2 * sl + (k & 1)];
        }
        a += __shfl_down_sync(0xffffffffu, a, 8, 16);
        a += __shfl_down_sync(0xffffffffu, a, 4, 16);
        a += __shfl_down_sync(0xffffffffu, a, 2, 16);
        a += __shfl_down_sync(0xffffffffu, a, 1, 16);
        if (kq == 0) out[b * OUTSZ + o] = a + bout[o];
    }
}

// =====================================================================
extern "C" void kernel_launch(void* const* d_in, const int* in_sizes, int n_in,
                              void* d_out, int out_size) {
    const float* x    = (const float*)d_in[0];
    const float* Wih  = (const float*)d_in[1];
    const float* Whh  = (const float*)d_in[2];
    const float* bih  = (const float*)d_in[3];
    const float* bhh  = (const float*)d_in[4];
    const float* Wout = (const float*)d_in[5];
    const float* bout = (const float*)d_in[6];
    float* out = (float*)d_out;

    pool_kernel<<<1792, 256>>>(x);                    // 14336 warps
    gi_kernel<<<dim3(24, 4, 2), 256>>>(Wih, bih);     // split-K, 192 CTAs
    gru_kernel<<<64, 256>>>(Whh, bhh, Wout, bout, out);  // 8 clusters x 8 CTAs
}

// round 14
// speedup vs baseline: 1.6077x; 1.0287x over previous
#include <cuda_runtime.h>
#include <cstdint>

#define HID   256
#define BB    8
#define TT    16
#define INSZ  784
#define OUTSZ 128

// scratch (no device allocs allowed)
__device__ float g_seq[TT * BB * INSZ];       // [t][b][784]
__device__ float g_giA[TT * BB * 3 * HID];    // k-half 0 partial (+bias)
__device__ float g_giB[TT * BB * 3 * HID];    // k-half 1 partial

typedef unsigned long long ull;

// ---------------- f32x2 helpers ----------------
__device__ __forceinline__ ull pk2(float a, float b) {
    ull r;
    asm("mov.b64 %0, {%1,%2};" : "=l"(r) : "f"(a), "f"(b));
    return r;
}
__device__ __forceinline__ float2 upk2(ull v) {
    float2 f;
    asm("mov.b64 {%0,%1}, %2;" : "=f"(f.x), "=f"(f.y) : "l"(v));
    return f;
}
__device__ __forceinline__ void ffma2(ull& d, ull a, ull b) {
    asm("fma.rn.f32x2 %0, %1, %2, %0;" : "+l"(d) : "l"(a), "l"(b));
}
__device__ __forceinline__ uint32_t smem_u32(const void* p) {
    uint32_t a;
    asm("{ .reg .u64 t; cvta.to.shared.u64 t, %1; cvt.u32.u64 %0, t; }"
        : "=r"(a) : "l"(p));
    return a;
}
__device__ __forceinline__ void cluster_sync_() {
    asm volatile("barrier.cluster.arrive.aligned;" ::: "memory");
    asm volatile("barrier.cluster.wait.aligned;"   ::: "memory");
}
// bulk DSMEM copy: local smem region -> same offset in peer CTA, completing
// with one tx on the peer's mbarrier.
__device__ __forceinline__ void bulk_to_peer(uint32_t dst_local, uint32_t src_local,
                                             unsigned bytes, uint32_t bar_local,
                                             int peer) {
    asm volatile(
        "{ .reg .b32 rd, rb;\n\t"
        "mapa.shared::cluster.u32 rd, %0, %3;\n\t"
        "mapa.shared::cluster.u32 rb, %2, %3;\n\t"
        "cp.async.bulk.shared::cluster.shared::cta.mbarrier::complete_tx::bytes "
        "[rd], [%1], %4, [rb];\n\t"
        "}"
        :: "r"(dst_local), "r"(src_local), "r"(bar_local), "r"(peer), "r"(bytes)
        : "memory");
}
__device__ __forceinline__ void fence_proxy_async_cta() {
    asm volatile("fence.proxy.async.shared::cta;" ::: "memory");
}
__device__ __forceinline__ void mbar_init(uint32_t bar, unsigned cnt) {
    asm volatile("mbarrier.init.shared.b64 [%0], %1;" :: "r"(bar), "r"(cnt) : "memory");
}
__device__ __forceinline__ void mbar_expect_tx(uint32_t bar, unsigned bytes) {
    asm volatile("mbarrier.arrive.expect_tx.shared.b64 _, [%0], %1;"
                 :: "r"(bar), "r"(bytes) : "memory");
}
__device__ __forceinline__ void mbar_wait_parity(uint32_t bar, unsigned parity) {
    asm volatile(
        "{ .reg .pred P;\n\t"
        "WL%=:\n\t"
        "mbarrier.try_wait.parity.acquire.cluster.shared::cta.b64 P, [%0], %1, 0x989680;\n\t"
        "@P bra WD%=;\n\t"
        "bra WL%=;\n\t"
        "WD%=:\n\t"
        "}"
        :: "r"(bar), "r"(parity) : "memory");
}
__device__ __forceinline__ float sigm(float x) {
    return 1.0f / (1.0f + __expf(-x));
}
__device__ __forceinline__ float tanh_fast(float x) {
    return 2.0f / (1.0f + __expf(-2.0f * x)) - 1.0f;
}

// =====================================================================
// Kernel 1: fused 3D+2D adaptive avg pool (proven; at DRAM/LTS knee).
// =====================================================================
__global__ void pool_kernel(const float* __restrict__ x) {
    int gwarp = (blockIdx.x * blockDim.x + threadIdx.x) >> 5;
    int lane  = threadIdx.x & 31;

    int h2 = gwarp % 7;  int tmp = gwarp / 7;
    int d2 = tmp % 16;   tmp /= 16;
    int c  = tmp % 16;   tmp /= 16;
    int b  = tmp;        // 0..7

    const float* base = x + ((long long)(b * 16 + c) * 32 + d2 * 2) * 12544
                          + h2 * 1792;

    float acc_a = 0.0f, acc_b = 0.0f;
    #pragma unroll
    for (int dd = 0; dd < 2; dd++) {
        #pragma unroll
        for (int pp = 0; pp < 8; pp++) {        // 8 row-pairs of 224 floats
            const float4* p4 = (const float4*)(base + dd * 12544 + pp * 224);
            float4 va = __ldcs(p4 + lane);
            acc_a += (va.x + va.y) + (va.z + va.w);
            if (lane < 24) {
                float4 vb = __ldcs(p4 + lane + 32);
                acc_b += (vb.x + vb.y) + (vb.z + vb.w);
            }
        }
    }
    float t1 = __shfl_up_sync(0xffffffffu, acc_b, 4);
    float t2 = __shfl_down_sync(0xffffffffu, acc_a, 28);
    float tot = acc_a + ((lane >= 4) ? t1 : t2);
    tot += __shfl_down_sync(0xffffffffu, tot, 2);
    tot += __shfl_down_sync(0xffffffffu, tot, 1);
    if (lane < 28 && (lane & 3) == 0) {
        int w2 = lane >> 2;
        g_seq[(d2 * BB + b) * INSZ + c * 49 + h2 * 7 + w2] = tot * (1.0f / 512.0f);
    }
}

// =====================================================================
// Kernel 2: gi partials, SPLIT-K (proven R11). grid (24, 4, 2).
// =====================================================================
__global__ void gi_kernel(const float* __restrict__ Wih,
                          const float* __restrict__ bih) {
    __shared__ __align__(16) float Ash[2][32][58];
    __shared__ __align__(16) float Bsh[2][32][58];

    int tid = threadIdx.x;
    int g0  = blockIdx.x * 32;
    int tb0 = blockIdx.y * 32;
    int kh  = blockIdx.z;             // 0 or 1
    int kb  = kh * 392;
    int tb  = tid & 31;
    int wid = tid >> 5;               // 0..7

    #pragma unroll
    for (int m = 0; m < 7; m++) {
        int i = tid + 256 * m;
        int r = i / 56, k = i % 56;
        Ash[0][r][k] = g_seq[(tb0 + r) * INSZ + kb + k];
        Bsh[0][r][k] = Wih[(long long)(g0 + r) * INSZ + kb + k];
    }
    __syncthreads();

    ull acc[4] = {0ull, 0ull, 0ull, 0ull};
    float ra[7], rb[7];

    for (int it = 0; it < 7; it++) {
        int cur = it & 1, nxt = cur ^ 1;
        if (it < 6) {
            int k0 = kb + (it + 1) * 56;
            #pragma unroll
            for (int m = 0; m < 7; m++) {
                int i = tid + 256 * m;
                int r = i / 56, k = i % 56;
                ra[m] = g_seq[(tb0 + r) * INSZ + k0 + k];
                rb[m] = Wih[(long long)(g0 + r) * INSZ + k0 + k];
            }
        }
        const ull* Ar = (const ull*)Ash[cur][tb];
        const ull* B0 = (const ull*)Bsh[cur][wid];
        const ull* B1 = (const ull*)Bsh[cur][wid + 8];
        const ull* B2 = (const ull*)Bsh[cur][wid + 16];
        const ull* B3 = (const ull*)Bsh[cur][wid + 24];
        #pragma unroll
        for (int kk = 0; kk < 28; kk++) {
            ull a2 = Ar[kk];
            ffma2(acc[0], a2, B0[kk]);
            ffma2(acc[1], a2, B1[kk]);
            ffma2(acc[2], a2, B2[kk]);
            ffma2(acc[3], a2, B3[kk]);
        }
        if (it < 6) {
            #pragma unroll
            for (int m = 0; m < 7; m++) {
                int i = tid + 256 * m;
                int r = i / 56, k = i % 56;
                Ash[nxt][r][k] = ra[m];
                Bsh[nxt][r][k] = rb[m];
            }
        }
        __syncthreads();
    }
    float* dst = (kh == 0) ? g_giA : g_giB;
    #pragma unroll
    for (int i = 0; i < 4; i++) {
        int g = g0 + wid + 8 * i;
        float2 f = upk2(acc[i]);
        float bias = (kh == 0) ? bih[g] : 0.0f;
        dst[(tb0 + tb) * (3 * HID) + g] = f.x + f.y + bias;
    }
}

// =====================================================================
// Kernel 3: GRU, one 8-CTA cluster PER BATCH.
// NEW exchange: h stored LINEARLY (hs[buf][j]); rank r owns the 128B
// region [32r, 32r+32). Per step each CTA sends its region to the 7
// peers with ONE cp.async.bulk each (7 tx arrivals of 128B; expect=896)
// instead of 128 st.async packets. Bank conflicts on the linear layout
// are avoided by ROTATED reads: thread (jl,s) reads slot 16s+((i+s)&15)
// (distinct banks across s; 4-way broadcast within s), with wp loaded
// pre-rotated to match. Ping-pong mbarrier parity scheme unchanged.
// =====================================================================
__global__ void __launch_bounds__(256, 1) __cluster_dims__(8, 1, 1)
gru_kernel(const float* __restrict__ Whh,
           const float* __restrict__ bhh,
           const float* __restrict__ Wout,
           const float* __restrict__ bout,
           float* __restrict__ out) {
    __shared__ __align__(16) float hs[3][264];   // linear h, triple-buffered
    __shared__ float gis[TT][96];    // gi[t][g*32+jl] for this (b, rank)
    __shared__ __align__(8) ull mbar[2];

    int tid  = threadIdx.x;
    int b    = blockIdx.x >> 3;      // batch = cluster id
    int rank = blockIdx.x & 7;       // cluster rank
    int jl   = tid >> 3;             // 0..31
    int s    = tid & 7;              // 0..7
    int j    = rank * 32 + jl;       // owned hidden unit

    // --- W_hh slice into registers, ROTATED: wp[g][m] = k-pair (m+s)&15
    //     of slice s (global k = s*32 + 2*((m+s)&15)) ---
    ull wp[3][16];
    #pragma unroll
    for (int g = 0; g < 3; g++) {
        const ull* wb = (const ull*)(Whh + (long long)(g * HID + j) * HID + s * 32);
        #pragma unroll
        for (int m = 0; m < 16; m++) wp[g][m] = wb[(m + s) & 15];
    }
    float bh0 = bhh[j], bh1 = bhh[HID + j], bh2 = bhh[2 * HID + j];

    // --- preload gi slice = sum of split-K partials ---
    #pragma unroll
    for (int i = tid; i < TT * 96; i += 256) {
        int t = i / 96, r = i % 96;
        int g = r >> 5, jj = r & 31;
        long long idx = (long long)(t * BB + b) * (3 * HID) + g * HID + rank * 32 + jj;
        gis[t][r] = g_giA[idx] + g_giB[idx];
    }
    // zero all 3 h buffers
    for (int q = tid; q < 3 * 264; q += 256) (&hs[0][0])[q] = 0.0f;

    uint32_t bar0 = smem_u32(&mbar[0]);
    uint32_t bar1 = smem_u32(&mbar[1]);
    if (tid == 0) {
        mbar_init(bar0, 1);
        mbar_init(bar1, 1);
        mbar_expect_tx(bar0, 896);        // 7 peers x 128B for step 0
    }
    __syncthreads();
    cluster_sync_();                      // barriers inited, buffers zeroed everywhere

    float hpv = 0.0f;                     // hprev for (b, j): all s identical

    for (int t = 0; t < TT; t++) {
        uint32_t barT = (t & 1) ? bar1 : bar0;
        if (tid == 0 && t < TT - 1)
            mbar_expect_tx((t & 1) ? bar0 : bar1, 896);   // for step t+1

        const ull* hb = (const ull*)hs[t % 3];
        int hbase = 16 * s;

        ull d0 = 0, d1 = 0, d2 = 0;
        #pragma unroll
        for (int i = 0; i < 16; i++) {
            ull h2 = hb[hbase + ((i + s) & 15)];
            ffma2(d0, wp[0][i], h2);
            ffma2(d1, wp[1][i], h2);
            ffma2(d2, wp[2][i], h2);
        }
        float2 f;
        f = upk2(d0);  float v0 = f.x + f.y;
        f = upk2(d1);  float v1 = f.x + f.y;
        f = upk2(d2);  float v2 = f.x + f.y;
        #pragma unroll
        for (int d = 4; d >= 1; d >>= 1) {
            v0 += __shfl_xor_sync(0xffffffffu, v0, d, 8);
            v1 += __shfl_xor_sync(0xffffffffu, v1, d, 8);
            v2 += __shfl_xor_sync(0xffffffffu, v2, d, 8);
        }

        // gate math on ALL threads (bit-identical across s)
        float r = sigm(gis[t][jl]      + v0 + bh0);
        float z = sigm(gis[t][32 + jl] + v1 + bh1);
        float n = tanh_fast(gis[t][64 + jl] + r * (v2 + bh2));
        float hnew = n + z * (hpv - n);
        hpv = hnew;

        // write own region of next buffer locally (s==0 lanes: 32 floats)
        float* hn = hs[(t + 1) % 3];
        if (s == 0) hn[j] = hnew;

        __syncthreads();   // own region written + expect posted, cluster-wide order next

        // 7 bulk copies: own 128B region -> same offset in each peer
        if (tid < 8 && tid != rank) {
            fence_proxy_async_cta();
            uint32_t reg = smem_u32(&hn[rank * 32]);
            bulk_to_peer(reg, reg, 128u, barT, tid);
        }

        mbar_wait_parity(barT, (t >> 1) & 1);
    }

    // ---- output head: final h (t=16) is in hs[16%3 = 1], LINEAR layout.
    {
        int ol = tid >> 4;           // 0..15
        int kq = tid & 15;           // 0..15
        int o  = rank * 16 + ol;
        const float* wo = Wout + (long long)o * HID;
        float a = 0.0f;
        #pragma unroll
        for (int m = 0; m < 16; m++) {
            int k = kq * 16 + m;
            a += wo[k] * hs[1][k];
        }
        a += __shfl_down_sync(0xffffffffu, a, 8, 16);
        a += __shfl_down_sync(0xffffffffu, a, 4, 16);
        a += __shfl_down_sync(0xffffffffu, a, 2, 16);
        a += __shfl_down_sync(0xffffffffu, a, 1, 16);
        if (kq == 0) out[b * OUTSZ + o] = a + bout[o];
    }
}

// =====================================================================
extern "C" void kernel_launch(void* const* d_in, const int* in_sizes, int n_in,
                              void* d_out, int out_size) {
    const float* x    = (const float*)d_in[0];
    const float* Wih  = (const float*)d_in[1];
    const float* Whh  = (const float*)d_in[2];
    const float* bih  = (const float*)d_in[3];
    const float* bhh  = (const float*)d_in[4];
    const float* Wout = (const float*)d_in[5];
    const float* bout = (const float*)d_in[6];
    float* out = (float*)d_out;

    pool_kernel<<<1792, 256>>>(x);                    // 14336 warps
    gi_kernel<<<dim3(24, 4, 2), 256>>>(Wih, bih);     // split-K, 192 CTAs
    gru_kernel<<<64, 256>>>(Whh, bhh, Wout, bout, out);  // 8 clusters x 8 CTAs
}